// round 3
// baseline (speedup 1.0000x reference)
#include <cuda_runtime.h>
#include <cstdint>
#include <cstddef>

#define NN 1024
#define BB 32

typedef unsigned long long c64;   // packed complex: lo=re, hi=im

// ---------------- device scratch (no allocations allowed) ----------------
static __device__ float2     g_tw[NN];         // scalar twiddles (hilbert)
static __device__ ulonglong2 g_twp[NN];        // packed: (wr,wr) , (-wi,wi)
static __device__ float2     g_pa[BB * NN];    // analytic signal (plain)
static __device__ ulonglong2 g_pa2[BB * NN];   // packed (ar,ar),(-ai,ai)
static __device__ c64        g_bb[BB * NN];    // pa * SHIFT_FACTOR, packed
static __device__ double     g_Sp[BB];
static __device__ double     g_Spt[BB];
static __device__ double     g_St[BB];
static __device__ double     g_Stt[BB];
static __device__ unsigned   g_M[BB];          // max shg (float bits)
static __device__ int        g_first[BB];
static __device__ int        g_last[BB];

__device__ __forceinline__ int br5(int j) {
    return (int)(__brev((unsigned)j) >> 27);
}

// ---------------- f32x2 packed helpers ------------------------------------
__device__ __forceinline__ c64 pk(float a, float b) {
    c64 r; asm("mov.b64 %0, {%1,%2};" : "=l"(r) : "f"(a), "f"(b)); return r;
}
__device__ __forceinline__ void unpk(c64 a, float& lo, float& hi) {
    asm("mov.b64 {%0,%1}, %2;" : "=f"(lo), "=f"(hi) : "l"(a));
}
__device__ __forceinline__ c64 cswap(c64 a) {
    float lo, hi; unpk(a, lo, hi); return pk(hi, lo);
}
__device__ __forceinline__ c64 add2(c64 a, c64 b) {
    c64 r; asm("add.rn.f32x2 %0,%1,%2;" : "=l"(r) : "l"(a), "l"(b)); return r;
}
__device__ __forceinline__ c64 mul2(c64 a, c64 b) {
    c64 r; asm("mul.rn.f32x2 %0,%1,%2;" : "=l"(r) : "l"(a), "l"(b)); return r;
}
__device__ __forceinline__ c64 fma2(c64 a, c64 b, c64 c) {
    c64 r; asm("fma.rn.f32x2 %0,%1,%2,%3;" : "=l"(r) : "l"(a), "l"(b), "l"(c));
    return r;
}

// ---------------- packed radix-2 DIF FFT-32 in registers ------------------
// input natural order, output bit-reversed: out[j] = X[brev5(j)]
__device__ __forceinline__ void fft32p(c64* x) {
    const float W32r[16] = {
        1.00000000f, 0.98078528f, 0.92387953f, 0.83146961f,
        0.70710678f, 0.55557023f, 0.38268343f, 0.19509032f,
        0.00000000f,-0.19509032f,-0.38268343f,-0.55557023f,
       -0.70710678f,-0.83146961f,-0.92387953f,-0.98078528f };
    const float W32i[16] = {
        0.00000000f,-0.19509032f,-0.38268343f,-0.55557023f,
       -0.70710678f,-0.83146961f,-0.92387953f,-0.98078528f,
       -1.00000000f,-0.98078528f,-0.92387953f,-0.83146961f,
       -0.70710678f,-0.55557023f,-0.38268343f,-0.19509032f };
    const c64 NEG1 = pk(-1.f, -1.f);
    const c64 P1M1 = pk(1.f, -1.f);
    #pragma unroll
    for (int st = 0; st < 5; st++) {
        const int h = 16 >> st;
        const int tstep = 1 << st;
        #pragma unroll
        for (int s = 0; s < 32; s += 2 * h) {
            #pragma unroll
            for (int j = 0; j < h; j++) {
                const int i0 = s + j, i1 = i0 + h;
                c64 u = x[i0], v = x[i1];
                x[i0] = add2(u, v);
                c64 d = fma2(v, NEG1, u);          // u - v
                const int w = j * tstep;
                if (w == 0) {
                    x[i1] = d;
                } else if (w == 8) {               // * (0,-1)
                    x[i1] = mul2(cswap(d), P1M1);
                } else {
                    c64 t = mul2(d, pk(W32r[w], W32r[w]));
                    x[i1] = fma2(cswap(d), pk(-W32i[w], W32i[w]), t);
                }
            }
        }
    }
}

// packed FFT-1024: lane t holds x[t+32q] in reg q; out reg j = X[lane+32*br5(j)]
__device__ __forceinline__ void fft1024p(c64* x, c64* sm, int lane) {
    fft32p(x);
    #pragma unroll
    for (int j = 0; j < 32; j++) {
        ulonglong2 w = g_twp[j * 32 + lane];
        c64 t = mul2(x[j], w.x);
        x[j] = fma2(cswap(x[j]), w.y, t);
    }
    __syncwarp();
    #pragma unroll
    for (int j = 0; j < 32; j++) sm[br5(j) * 33 + lane] = x[j];
    __syncwarp();
    #pragma unroll
    for (int r = 0; r < 32; r++) x[r] = sm[lane * 33 + r];
    __syncwarp();
    fft32p(x);
}

// ---------------- scalar FFT (k_hilbert only) ------------------------------
__device__ __forceinline__ void fft32(float* ar, float* ai) {
    const float W32r[16] = {
        1.00000000f, 0.98078528f, 0.92387953f, 0.83146961f,
        0.70710678f, 0.55557023f, 0.38268343f, 0.19509032f,
        0.00000000f,-0.19509032f,-0.38268343f,-0.55557023f,
       -0.70710678f,-0.83146961f,-0.92387953f,-0.98078528f };
    const float W32i[16] = {
        0.00000000f,-0.19509032f,-0.38268343f,-0.55557023f,
       -0.70710678f,-0.83146961f,-0.92387953f,-0.98078528f,
       -1.00000000f,-0.98078528f,-0.92387953f,-0.83146961f,
       -0.70710678f,-0.55557023f,-0.38268343f,-0.19509032f };
    #pragma unroll
    for (int st = 0; st < 5; st++) {
        const int h = 16 >> st;
        const int tstep = 1 << st;
        #pragma unroll
        for (int s = 0; s < 32; s += 2 * h) {
            #pragma unroll
            for (int j = 0; j < h; j++) {
                const int i0 = s + j, i1 = i0 + h;
                float ur = ar[i0], ui = ai[i0];
                float vr = ar[i1], vi = ai[i1];
                ar[i0] = ur + vr; ai[i0] = ui + vi;
                float dr = ur - vr, di = ui - vi;
                const int w = j * tstep;
                if (w == 0)      { ar[i1] = dr;  ai[i1] = di;  }
                else if (w == 8) { ar[i1] = di;  ai[i1] = -dr; }
                else {
                    float wr = W32r[w], wi = W32i[w];
                    ar[i1] = dr * wr - di * wi;
                    ai[i1] = di * wr + dr * wi;
                }
            }
        }
    }
}

__device__ __forceinline__ void fft1024s(float* xr, float* xi,
                                         float* sm, int lane) {
    fft32(xr, xi);
    #pragma unroll
    for (int j = 0; j < 32; j++) {
        float2 w = g_tw[j * 32 + lane];
        float r = xr[j] * w.x - xi[j] * w.y;
        xi[j]   = xi[j] * w.x + xr[j] * w.y;
        xr[j]   = r;
    }
    __syncwarp();
    #pragma unroll
    for (int j = 0; j < 32; j++) sm[br5(j) * 33 + lane] = xr[j];
    __syncwarp();
    #pragma unroll
    for (int r = 0; r < 32; r++) xr[r] = sm[lane * 33 + r];
    __syncwarp();
    #pragma unroll
    for (int j = 0; j < 32; j++) sm[br5(j) * 33 + lane] = xi[j];
    __syncwarp();
    #pragma unroll
    for (int r = 0; r < 32; r++) xi[r] = sm[lane * 33 + r];
    __syncwarp();
    fft32(xr, xi);
}

__device__ __forceinline__ c64 mkc(float lo, float hi) {
    return ((c64)__float_as_uint(hi) << 32) | (c64)__float_as_uint(lo);
}

// ---------------- K0: twiddles + bounds + accumulator reset ---------------
__global__ void __launch_bounds__(256) k_init(const float* __restrict__ label,
                                              float* __restrict__ out) {
    int tid = threadIdx.x, lane = tid & 31, warp = tid >> 5;
    if (blockIdx.x == 32) {
        for (int i = tid; i < NN; i += 256) {
            int j = i >> 5, t = i & 31;
            int e = (t * br5(j)) & 1023;
            float s, c;
            sincospif(-(float)e * (1.0f / 512.0f), &s, &c);
            g_tw[i] = make_float2(c, s);
            g_twp[i] = make_ulonglong2(mkc(c, c), mkc(-s, s));
        }
        if (tid < BB) {
            g_Sp[tid] = 0.0; g_Spt[tid] = 0.0;
            g_St[tid] = 0.0; g_Stt[tid] = 0.0;
            g_M[tid] = 0u;
        }
        if (tid == 0) out[0] = 0.f;
        return;
    }
    // bounds for batch b
    __shared__ int s_fr[8], s_lr[8], s_fi[8], s_li[8];
    int b = blockIdx.x;
    const float* lab = label + b * 2 * NN;
    int fr = NN, lr2 = -1, fi = NN, li2 = -1;
    #pragma unroll
    for (int q = 0; q < 4; q++) {
        int t = tid + 256 * q;
        float lr = lab[t], li = lab[NN + t];
        if (fabsf(lr) > 0.01f) { fr = min(fr, t); lr2 = max(lr2, t); }
        if (fabsf(li) > 0.01f) { fi = min(fi, t); li2 = max(li2, t); }
    }
    #pragma unroll
    for (int o = 16; o; o >>= 1) {
        fr  = min(fr,  __shfl_xor_sync(0xffffffffu, fr, o));
        lr2 = max(lr2, __shfl_xor_sync(0xffffffffu, lr2, o));
        fi  = min(fi,  __shfl_xor_sync(0xffffffffu, fi, o));
        li2 = max(li2, __shfl_xor_sync(0xffffffffu, li2, o));
    }
    if (lane == 0) { s_fr[warp] = fr; s_lr[warp] = lr2; s_fi[warp] = fi; s_li[warp] = li2; }
    __syncthreads();
    if (tid == 0) {
        int FR = NN, LR = -1, FI = NN, LI = -1;
        #pragma unroll
        for (int i = 0; i < 8; i++) {
            FR = min(FR, s_fr[i]); LR = max(LR, s_lr[i]);
            FI = min(FI, s_fi[i]); LI = max(LI, s_li[i]);
        }
        if (FR == NN) FR = 0;
        if (FI == NN) FI = 0;
        if (LR < 0)   LR = NN - 1;
        if (LI < 0)   LI = NN - 1;
        g_first[b] = min(FR, FI);
        g_last[b]  = max(LR, LI);
    }
}

// ---------------- K1: Hilbert + SHIFT_FACTOR fold + packed prep -----------
__global__ void __launch_bounds__(128) k_hilbert(const float* __restrict__ pred) {
    __shared__ float sm[4][33 * 32];
    int warp = threadIdx.x >> 5, lane = threadIdx.x & 31;
    int b = blockIdx.x * 4 + warp;

    float xr[32], xi[32];
    const float* p = pred + b * NN;
    #pragma unroll
    for (int q = 0; q < 32; q++) { xr[q] = p[lane + 32 * q]; xi[q] = 0.f; }

    fft1024s(xr, xi, sm[warp], lane);

    float yr[32], yi[32];
    #pragma unroll
    for (int p2 = 0; p2 < 32; p2++) {
        int j = br5(p2);
        int k = lane + 32 * p2;
        float f = (k > 512) ? 2.f : ((k == 512) ? 1.f : 0.f);
        yr[p2] =  xr[j] * f;
        yi[p2] = -xi[j] * f;
    }
    fft1024s(yr, yi, sm[warp], lane);   // ifft via conj trick

    const float phi = (float)(2.0 * 1.175e15 * 1.5e-15);
    #pragma unroll
    for (int j = 0; j < 32; j++) {
        int m = lane + 32 * br5(j);
        float prr =  yr[j] * (1.f / 1024.f);
        float pii = -yi[j] * (1.f / 1024.f);
        g_pa[b * NN + m]  = make_float2(prr, pii);
        g_pa2[b * NN + m] = make_ulonglong2(mkc(prr, prr), mkc(-pii, pii));
        float argf = phi * (float)(m - 512);
        float si, cr;
        sincosf(argf, &si, &cr);                 // SF = cr - i*si
        g_bb[b * NN + m] = mkc(prr * cr + pii * si,
                               pii * cr - prr * si);
    }
}

// ---------------- K2: SHG rows — packed FFT + streaming reduction ---------
__global__ void __launch_bounds__(128) k_shg(const float* __restrict__ tref) {
    __shared__ c64 sm[4][33 * 32];
    __shared__ float s_acc[4][4];
    __shared__ float s_mx[4];
    int warp = threadIdx.x >> 5, lane = threadIdx.x & 31;
    int w = blockIdx.x * 4 + warp;
    int b = w >> 10;
    int d = w & 1023;

    const c64* pb = g_bb + b * NN;
    const ulonglong2* pa2 = g_pa2 + b * NN;
    c64 x[32];
    #pragma unroll
    for (int q = 0; q < 32; q++) {
        int n = lane + 32 * q;
        c64 bv = pb[n];
        ulonglong2 aw = pa2[(n - d + 512) & 1023];
        c64 t = mul2(bv, aw.x);
        x[q] = fma2(cswap(bv), aw.y, t);
    }

    fft1024p(x, sm[warp], lane);

    const float* trow = tref + (size_t)(b * 1024 + d) * 1024;
    float sp = 0.f, spt = 0.f, st = 0.f, stt = 0.f, mx = 0.f;
    #pragma unroll
    for (int j = 0; j < 32; j++) {
        c64 sq = mul2(x[j], x[j]);
        float re2, im2; unpk(sq, re2, im2);
        float m = re2 + im2;
        int col = (lane + 32 * br5(j) + 512) & 1023;
        float tv = __ldcs(trow + col);
        sp += m; spt += m * tv; st += tv; stt += tv * tv;
        mx = fmaxf(mx, m);
    }
    #pragma unroll
    for (int o = 16; o; o >>= 1) {
        sp  += __shfl_xor_sync(0xffffffffu, sp, o);
        spt += __shfl_xor_sync(0xffffffffu, spt, o);
        st  += __shfl_xor_sync(0xffffffffu, st, o);
        stt += __shfl_xor_sync(0xffffffffu, stt, o);
        mx = fmaxf(mx, __shfl_xor_sync(0xffffffffu, mx, o));
    }
    if (lane == 0) {
        s_acc[warp][0] = sp; s_acc[warp][1] = spt;
        s_acc[warp][2] = st; s_acc[warp][3] = stt;
        s_mx[warp] = mx;
    }
    __syncthreads();
    if (threadIdx.x == 0) {
        double a0 = 0, a1 = 0, a2 = 0, a3 = 0; float mm = 0.f;
        #pragma unroll
        for (int i2 = 0; i2 < 4; i2++) {
            a0 += (double)s_acc[i2][0]; a1 += (double)s_acc[i2][1];
            a2 += (double)s_acc[i2][2]; a3 += (double)s_acc[i2][3];
            mm = fmaxf(mm, s_mx[i2]);
        }
        atomicAdd(&g_Sp[b],  a0);
        atomicAdd(&g_Spt[b], a1);
        atomicAdd(&g_St[b],  a2);
        atomicAdd(&g_Stt[b], a3);
        atomicMax(&g_M[b], __float_as_uint(mm));
    }
}

// ---------------- K3: MSE + FROG, parallel atomic mean --------------------
__global__ void __launch_bounds__(256) k_loss(const float* __restrict__ label,
                                              float* __restrict__ out) {
    __shared__ float s_s[8];
    int tid = threadIdx.x, lane = tid & 31, warp = tid >> 5;
    int b = blockIdx.x >> 2;
    int chunk = blockIdx.x & 3;
    int t = chunk * 256 + tid;
    const float* lab = label + b * 2 * NN;
    int first = g_first[b], last = g_last[b];

    float2 pav = g_pa[b * NN + t];
    float pr = pav.x, pi = pav.y;
    float lr = lab[t], li = lab[NN + t];
    bool inr = (t >= first) && (t < last);
    float pm = inr ? 10.f : 1.f;
    float d1 = pr - lr, d2 = pi - li;
    float d3 = (pr * pr + pi * pi) - (lr * lr + li * li);
    float dph = atan2f(pi, pr) - atan2f(li, lr);
    float s = (d1 * d1 + d2 * d2 + d3 * d3) * pm + (inr ? dph * dph : 0.f);

    #pragma unroll
    for (int o = 16; o; o >>= 1) s += __shfl_xor_sync(0xffffffffu, s, o);
    if (lane == 0) s_s[warp] = s;
    __syncthreads();
    if (tid == 0) {
        float ss = 0.f;
        #pragma unroll
        for (int i = 0; i < 8; i++) ss += s_s[i];
        float v = ss * (1.f / (4.f * 1024.f * 32.f));  // /N /WSUM /B
        if (chunk == 0) {
            double M   = (double)__uint_as_float(g_M[b]);
            double mu  = (g_Spt[b] / M) / g_Stt[b];
            double dif = g_Sp[b] / M - mu * g_St[b];
            v += (float)(fabs(dif) * (1.0 / 1024.0)) * (1.f / 32.f);
        }
        atomicAdd(out, v);
    }
}

// ---------------- launch ---------------------------------------------------
extern "C" void kernel_launch(void* const* d_in, const int* in_sizes, int n_in,
                              void* d_out, int out_size) {
    (void)in_sizes; (void)n_in; (void)out_size;
    const float* pred  = (const float*)d_in[0];   // (32, 1024)
    const float* label = (const float*)d_in[1];   // (32, 2048)
    const float* shg   = (const float*)d_in[2];   // (32, 1, 1024, 1024)
    float* out = (float*)d_out;

    k_init<<<33, 256>>>(label, out);
    k_hilbert<<<8, 128>>>(pred);
    k_shg<<<8192, 128>>>(shg);
    k_loss<<<128, 256>>>(label, out);
}